// round 15
// baseline (speedup 1.0000x reference)
#include <cuda_runtime.h>
#include <cuda_fp16.h>
#include <cstdint>
#include <math.h>

#define NMAX 20000
#define EMAX 320000
#define D 512

// ---------------- scratch (static device globals; no allocation) -------------
__device__ __half g_H16 [NMAX * D];
__device__ __half g_R16 [NMAX * D];
__device__ __half g_F16 [NMAX * D];
__device__ __half g_FT16[NMAX * D];      // feat in fp16
// fp16 weights [N][K]: fc, W1'(l1), W2'(l1), W1'(l2), W2'(l2)  (residual folded)
__device__ __half g_W16 [5 * D * D];
__device__ float  g_norm[NMAX];
__device__ int    g_cnt [NMAX];          // zero-init; scan re-zeroes each call
__device__ int    g_off [NMAX + 1];
__device__ int    g_cur [NMAX + 1];
__device__ int    g_csr [EMAX];

// ================= small helpers ==============================================
__device__ __forceinline__ void cp16(uint32_t dst, const void* src, int bytes)
{
    asm volatile("cp.async.cg.shared.global [%0], [%1], 16, %2;"
                 :: "r"(dst), "l"(src), "r"(bytes));
}
__device__ __forceinline__ void cp_commit() { asm volatile("cp.async.commit_group;"); }
template <int N> __device__ __forceinline__ void cp_wait()
{ asm volatile("cp.async.wait_group %0;" :: "n"(N)); }

__device__ __forceinline__ void mma16(float* c,
                                      unsigned a0, unsigned a1, unsigned a2, unsigned a3,
                                      unsigned b0, unsigned b1)
{
    asm volatile(
        "mma.sync.aligned.m16n8k16.row.col.f32.f16.f16.f32 "
        "{%0,%1,%2,%3},{%4,%5,%6,%7},{%8,%9},{%0,%1,%2,%3};"
        : "+f"(c[0]), "+f"(c[1]), "+f"(c[2]), "+f"(c[3])
        : "r"(a0), "r"(a1), "r"(a2), "r"(a3), "r"(b0), "r"(b1));
}

__device__ __forceinline__ void ldsm4(unsigned& r0, unsigned& r1, unsigned& r2, unsigned& r3,
                                      uint32_t addr)
{
    asm volatile("ldmatrix.sync.aligned.m8n8.x4.shared.b16 {%0,%1,%2,%3}, [%4];"
                 : "=r"(r0), "=r"(r1), "=r"(r2), "=r"(r3) : "r"(addr));
}

// ================= fused prep =================================================
// deg histogram | feat->fp16 | fcw->fp16 | layer weights: transpose + fold
// W1' = beta*W1 + (1-beta)*I ;  W2' = 0.1*(beta*W2 + (1-beta)*I)
__global__ __launch_bounds__(256)
void prep_all(const int* __restrict__ dst, int* __restrict__ cnt, int E, int nbd,
              const float* __restrict__ feat, __half* __restrict__ f16, int featN, int nbf,
              const float* __restrict__ fcw,
              const float* __restrict__ w11, const float* __restrict__ w21,
              const float* __restrict__ w12, const float* __restrict__ w22,
              __half* __restrict__ w16)
{
    __shared__ float tile[32][33];
    const int b = blockIdx.x, tid = threadIdx.x;

    if (b < nbd) {                                   // degree histogram
        int i = b * 256 + tid;
        if (i < E) atomicAdd(cnt + __ldg(dst + i), 1);
        return;
    }
    if (b < nbd + nbf) {                             // feat -> fp16
        int i = (b - nbd) * 2048 + tid * 8;
        if (i + 8 <= featN) {
            float4 a = *reinterpret_cast<const float4*>(feat + i);
            float4 c = *reinterpret_cast<const float4*>(feat + i + 4);
            __half2 h0 = __floats2half2_rn(a.x, a.y);
            __half2 h1 = __floats2half2_rn(a.z, a.w);
            __half2 h2 = __floats2half2_rn(c.x, c.y);
            __half2 h3 = __floats2half2_rn(c.z, c.w);
            uint4 o;
            o.x = *reinterpret_cast<uint32_t*>(&h0);
            o.y = *reinterpret_cast<uint32_t*>(&h1);
            o.z = *reinterpret_cast<uint32_t*>(&h2);
            o.w = *reinterpret_cast<uint32_t*>(&h3);
            *reinterpret_cast<uint4*>(f16 + i) = o;
        }
        return;
    }
    if (b < nbd + nbf + 128) {                       // fc_w -> fp16 (already [N][K])
        int i = (b - nbd - nbf) * 2048 + tid * 8;
        float4 a = *reinterpret_cast<const float4*>(fcw + i);
        float4 c = *reinterpret_cast<const float4*>(fcw + i + 4);
        __half2 h0 = __floats2half2_rn(a.x, a.y);
        __half2 h1 = __floats2half2_rn(a.z, a.w);
        __half2 h2 = __floats2half2_rn(c.x, c.y);
        __half2 h3 = __floats2half2_rn(c.z, c.w);
        uint4 o;
        o.x = *reinterpret_cast<uint32_t*>(&h0);
        o.y = *reinterpret_cast<uint32_t*>(&h1);
        o.z = *reinterpret_cast<uint32_t*>(&h2);
        o.w = *reinterpret_cast<uint32_t*>(&h3);
        *reinterpret_cast<uint4*>(w16 + i) = o;
        return;
    }
    // layer weights [K][N] -> [N][K] fp16, residual folded
    const float beta1 = 0.69314718056f;   // log(2)
    const float beta2 = 0.40546510811f;   // log(1.5)
    int b2  = b - nbd - nbf - 128;
    int mat = b2 >> 8;
    int rem = b2 & 255;
    int n0 = (rem & 15) * 32, k0 = (rem >> 4) * 32;
    int tx = tid & 31, ty = tid >> 5;
    const float* s;
    float bsc, idadd;
    if      (mat == 0) { s = w11; bsc = beta1;        idadd = 1.0f - beta1; }
    else if (mat == 1) { s = w21; bsc = 0.1f * beta1; idadd = 0.1f * (1.0f - beta1); }
    else if (mat == 2) { s = w12; bsc = beta2;        idadd = 1.0f - beta2; }
    else               { s = w22; bsc = 0.1f * beta2; idadd = 0.1f * (1.0f - beta2); }
    __half* dstw = w16 + (size_t)(mat + 1) * D * D;
    #pragma unroll
    for (int j = 0; j < 4; j++)
        tile[ty + j * 8][tx] = s[(size_t)(k0 + ty + j * 8) * D + n0 + tx];
    __syncthreads();
    #pragma unroll
    for (int j = 0; j < 4; j++) {
        int nn = n0 + ty + j * 8;
        int kk = k0 + tx;
        float v = tile[tx][ty + j * 8] * bsc + ((nn == kk) ? idadd : 0.0f);
        dstw[(size_t)nn * D + kk] = __float2half(v);
    }
}

// ================= scan: warp-shuffle prefix + cur + norm + cnt re-zero =======
__global__ void scan_kernel(int* __restrict__ cnt, int* __restrict__ off,
                            int* __restrict__ cur, float* __restrict__ norm, int n)
{
    __shared__ int sh[32];
    const int CH = 20;
    int t = threadIdx.x;
    int lane = t & 31, wid = t >> 5;
    int base = t * CH;
    int v[CH];
    if (base + CH <= n) {
        #pragma unroll
        for (int i = 0; i < CH / 4; i++) {
            int4 q = *reinterpret_cast<const int4*>(cnt + base + i * 4);
            v[i * 4 + 0] = q.x; v[i * 4 + 1] = q.y;
            v[i * 4 + 2] = q.z; v[i * 4 + 3] = q.w;
        }
    } else {
        #pragma unroll
        for (int i = 0; i < CH; i++) v[i] = (base + i < n) ? cnt[base + i] : 0;
    }
    int s = 0;
    #pragma unroll
    for (int i = 0; i < CH; i++) s += v[i];

    // warp inclusive scan
    int incl = s;
    #pragma unroll
    for (int d = 1; d < 32; d <<= 1) {
        int x = __shfl_up_sync(0xFFFFFFFFu, incl, d);
        if (lane >= d) incl += x;
    }
    if (lane == 31) sh[wid] = incl;
    __syncthreads();
    if (wid == 0) {
        int w = sh[lane];
        int wincl = w;
        #pragma unroll
        for (int d = 1; d < 32; d <<= 1) {
            int x = __shfl_up_sync(0xFFFFFFFFu, wincl, d);
            if (lane >= d) wincl += x;
        }
        sh[lane] = wincl - w;    // exclusive warp prefix
    }
    __syncthreads();
    int run = sh[wid] + incl - s;    // exclusive prefix for this thread

    int offv[CH];
    float nv[CH];
    #pragma unroll
    for (int i = 0; i < CH; i++) {
        offv[i] = run;
        nv[i]   = rsqrtf(fmaxf((float)v[i], 1.0f));
        run += v[i];
    }
    if (base + CH <= n) {
        #pragma unroll
        for (int i = 0; i < CH; i += 4) {
            int4 o = make_int4(offv[i], offv[i + 1], offv[i + 2], offv[i + 3]);
            *reinterpret_cast<int4*>(off + base + i) = o;
            *reinterpret_cast<int4*>(cur + base + i) = o;
            *reinterpret_cast<float4*>(norm + base + i) =
                make_float4(nv[i], nv[i + 1], nv[i + 2], nv[i + 3]);
            *reinterpret_cast<int4*>(cnt + base + i) = make_int4(0, 0, 0, 0);
        }
    } else {
        for (int i = 0; i < CH; i++) {
            int idx = base + i;
            if (idx < n) {
                off[idx] = offv[i]; cur[idx] = offv[i]; norm[idx] = nv[i];
                cnt[idx] = 0;
            }
        }
    }
    if (t == 1023) off[n] = run;
}

__global__ void fill_kernel(const int* __restrict__ src, const int* __restrict__ dst,
                            int* __restrict__ cur, int* __restrict__ csr, int E)
{
    int i = blockIdx.x * blockDim.x + threadIdx.x;
    if (i < E) {
        int d = __ldg(dst + i);
        int p = atomicAdd(cur + d, 1);
        csr[p] = __ldg(src + i);
    }
}

// ================= aggregation: fp16 gather -> fp16 out ======================
__global__ __launch_bounds__(128)
void agg_kernel(const __half* __restrict__ h, const float* __restrict__ norm,
                const int* __restrict__ off, const int* __restrict__ csr,
                __half* __restrict__ F)
{
    int node = blockIdx.x;
    int c    = threadIdx.x * 4;
    int s0 = __ldg(off + node);
    int s1 = __ldg(off + node + 1);
    float4 acc = make_float4(0.f, 0.f, 0.f, 0.f);
    int j = s0;
    for (; j + 3 < s1; j += 4) {
        int   si[4];
        float wi[4];
        #pragma unroll
        for (int u = 0; u < 4; u++) si[u] = __ldg(csr + j + u);
        #pragma unroll
        for (int u = 0; u < 4; u++) wi[u] = __ldg(norm + si[u]);
        uint2 q[4];
        #pragma unroll
        for (int u = 0; u < 4; u++)
            q[u] = *reinterpret_cast<const uint2*>(h + (size_t)si[u] * D + c);
        #pragma unroll
        for (int u = 0; u < 4; u++) {
            float2 lo = __half22float2(*reinterpret_cast<__half2*>(&q[u].x));
            float2 hi = __half22float2(*reinterpret_cast<__half2*>(&q[u].y));
            acc.x += wi[u] * lo.x;
            acc.y += wi[u] * lo.y;
            acc.z += wi[u] * hi.x;
            acc.w += wi[u] * hi.y;
        }
    }
    for (; j < s1; j++) {
        int sA = __ldg(csr + j);
        float wA = __ldg(norm + sA);
        uint2 q = *reinterpret_cast<const uint2*>(h + (size_t)sA * D + c);
        float2 lo = __half22float2(*reinterpret_cast<__half2*>(&q.x));
        float2 hi = __half22float2(*reinterpret_cast<__half2*>(&q.y));
        acc.x += wA * lo.x; acc.y += wA * lo.y;
        acc.z += wA * hi.x; acc.w += wA * hi.y;
    }
    float wn = __ldg(norm + node) * 0.9f;
    __half2 lo = __floats2half2_rn(acc.x * wn, acc.y * wn);
    __half2 hi = __floats2half2_rn(acc.z * wn, acc.w * wn);
    uint2 o;
    o.x = *reinterpret_cast<uint32_t*>(&lo);
    o.y = *reinterpret_cast<uint32_t*>(&hi);
    *reinterpret_cast<uint2*>(F + (size_t)node * D + c) = o;
}

// ================= unified fp16 GEMM (cp.async + ldmatrix, m16n8k16) =========
// CTA tile 64(M) x 128(N); SMEM rows stride 80 B; 4-stage pipeline.
// Per stage: A 64x32 halves (5120 B), B 128x32 halves (10240 B).
#define STG 4
#define TA16 5120
#define TB16 10240

// LAYER=false: out16 = half(A0@B0^T + bias)                (T=16)
// LAYER=true:  out = relu(A0@B0' + A1@B1' + bias)          (T=32, weights folded)
template <bool LAYER, bool OUT32>
__global__ __launch_bounds__(256, 2)
void gemm16(const __half* __restrict__ A0, const __half* __restrict__ A1,
            const __half* __restrict__ B0, const __half* __restrict__ B1,
            const float* __restrict__ bias, float* __restrict__ C,
            __half* __restrict__ C16, int M)
{
    extern __shared__ unsigned sm[];
    const int tid = threadIdx.x, lane = tid & 31, warp = tid >> 5;
    const int wm = warp >> 2, wn = warp & 3;      // 2 x 4 warp grid
    const int bm = blockIdx.y * 64, bn = blockIdx.x * 128;
    const uint32_t smb  = (uint32_t)__cvta_generic_to_shared(sm);
    const uint32_t smbB = smb + STG * TA16;

    float acc[2][4][4] = {};

    // A loader: 256 chunks, 1/thread. B loader: 512 chunks, 2/thread.
    const int arow = tid >> 2, ach = tid & 3;
    const int aval = (bm + arow < M) ? 16 : 0;
    const uint32_t dA = smb + (uint32_t)(arow * 80 + ach * 16);
    int brow[2], bch[2];
    uint32_t dB[2];
    #pragma unroll
    for (int i = 0; i < 2; i++) {
        int cid = tid + i * 256;
        brow[i] = cid >> 2;
        bch[i]  = cid & 3;
        dB[i] = smbB + (uint32_t)(brow[i] * 80 + bch[i] * 16);
    }

    auto issue = [&](int stage, int t) {
        const __half* Ap;
        const __half* Bp;
        int k0;
        if (LAYER) {
            bool second = (t >= 16);
            Ap = second ? A1 : A0;
            Bp = second ? B1 : B0;
            k0 = (t & 15) * 32;
        } else {
            Ap = A0; Bp = B0; k0 = t * 32;
        }
        const __half* as = Ap + (size_t)(aval ? bm + arow : 0) * D + k0 + ach * 8;
        cp16(dA + (uint32_t)stage * TA16, as, aval);
        #pragma unroll
        for (int i = 0; i < 2; i++) {
            const __half* bs = Bp + (size_t)(bn + brow[i]) * D + k0 + bch[i] * 8;
            cp16(dB[i] + (uint32_t)stage * TB16, bs, 16);
        }
        cp_commit();
    };

    uint32_t aoff[2];
    #pragma unroll
    for (int mt = 0; mt < 2; mt++) {
        int row = wm * 32 + mt * 16 + (lane & 15);
        aoff[mt] = (uint32_t)(row * 80 + ((lane >> 4) & 1) * 16);
    }
    uint32_t boff[2];
    #pragma unroll
    for (int np = 0; np < 2; np++) {
        int row = wn * 32 + np * 16 + (lane & 7) + ((lane & 16) ? 8 : 0);
        boff[np] = (uint32_t)(row * 80 + ((lane >> 3) & 1) * 16);
    }

    auto compute = [&](int stage) {
        uint32_t sa = smb  + (uint32_t)stage * TA16;
        uint32_t sb = smbB + (uint32_t)stage * TB16;
        #pragma unroll
        for (int kc = 0; kc < 2; kc++) {
            unsigned af[2][4], bf[4][2];
            #pragma unroll
            for (int mt = 0; mt < 2; mt++)
                ldsm4(af[mt][0], af[mt][1], af[mt][2], af[mt][3],
                      sa + aoff[mt] + kc * 32);
            #pragma unroll
            for (int np = 0; np < 2; np++)
                ldsm4(bf[2 * np][0], bf[2 * np][1], bf[2 * np + 1][0], bf[2 * np + 1][1],
                      sb + boff[np] + kc * 32);
            #pragma unroll
            for (int mt = 0; mt < 2; mt++)
                #pragma unroll
                for (int nt = 0; nt < 4; nt++)
                    mma16(acc[mt][nt], af[mt][0], af[mt][1], af[mt][2], af[mt][3],
                          bf[nt][0], bf[nt][1]);
        }
    };

    const int T = LAYER ? 32 : 16;
    #pragma unroll
    for (int p = 0; p < STG - 1; p++) issue(p, p);
    for (int t = 0; t < T; t++) {
        cp_wait<STG - 2>();
        __syncthreads();
        if (t + STG - 1 < T) issue((t + STG - 1) % STG, t + STG - 1);
        else                 cp_commit();
        compute(t % STG);
    }

    const int grp = lane >> 2, tig = lane & 3;
    #pragma unroll
    for (int mt = 0; mt < 2; mt++) {
        int gr[2];
        gr[0] = bm + wm * 32 + mt * 16 + grp;
        gr[1] = gr[0] + 8;
        #pragma unroll
        for (int nt = 0; nt < 4; nt++) {
            int gc = bn + wn * 32 + nt * 8 + tig * 2;
            float2 bb = *reinterpret_cast<const float2*>(bias + gc);
            #pragma unroll
            for (int hh = 0; hh < 2; hh++) {
                if (gr[hh] >= M) continue;
                size_t base = (size_t)gr[hh] * D + gc;
                float2 v;
                v.x = acc[mt][nt][2 * hh + 0] + bb.x;
                v.y = acc[mt][nt][2 * hh + 1] + bb.y;
                if (LAYER) {
                    v.x = fmaxf(v.x, 0.f);
                    v.y = fmaxf(v.y, 0.f);
                }
                if (OUT32)
                    *reinterpret_cast<float2*>(C + base) = v;
                else
                    *reinterpret_cast<__half2*>(C16 + base) = __floats2half2_rn(v.x, v.y);
            }
        }
    }
}

// ================= host orchestration =========================================
extern "C" void kernel_launch(void* const* d_in, const int* in_sizes, int n_in,
                              void* d_out, int out_size)
{
    const float* feat = (const float*)d_in[0];
    const int*   src  = (const int*)  d_in[1];
    const int*   dst  = (const int*)  d_in[2];
    const float* fc_w = (const float*)d_in[3];
    const float* fc_b = (const float*)d_in[4];
    const float* w1_1 = (const float*)d_in[5];
    const float* w2_1 = (const float*)d_in[6];
    const float* b_1  = (const float*)d_in[7];
    const float* w1_2 = (const float*)d_in[8];
    const float* w2_2 = (const float*)d_in[9];
    const float* b_2  = (const float*)d_in[10];
    float* out = (float*)d_out;

    int M = in_sizes[0] / D;
    int E = in_sizes[1];

    float *NORM;
    __half *H16, *R16, *F16, *FT16, *W16;
    int *CNT, *OFF, *CUR, *CSR;
    cudaGetSymbolAddress((void**)&H16,  g_H16);
    cudaGetSymbolAddress((void**)&R16,  g_R16);
    cudaGetSymbolAddress((void**)&F16,  g_F16);
    cudaGetSymbolAddress((void**)&FT16, g_FT16);
    cudaGetSymbolAddress((void**)&W16,  g_W16);
    cudaGetSymbolAddress((void**)&NORM, g_norm);
    cudaGetSymbolAddress((void**)&CNT,  g_cnt);
    cudaGetSymbolAddress((void**)&OFF,  g_off);
    cudaGetSymbolAddress((void**)&CUR,  g_cur);
    cudaGetSymbolAddress((void**)&CSR,  g_csr);

    const int smem = STG * (TA16 + TB16);     // 61440
    cudaFuncSetAttribute((const void*)gemm16<false, false>, cudaFuncAttributeMaxDynamicSharedMemorySize, smem);
    cudaFuncSetAttribute((const void*)gemm16<true,  false>, cudaFuncAttributeMaxDynamicSharedMemorySize, smem);
    cudaFuncSetAttribute((const void*)gemm16<true,  true >, cudaFuncAttributeMaxDynamicSharedMemorySize, smem);

    dim3 grid(D / 128, (M + 63) / 64);

    int featN = M * D;
    int nbd = (E + 255) / 256;
    int nbf = (featN + 2047) / 2048;
    int nb_total = nbd + nbf + 128 + 1024;

    prep_all<<<nb_total, 256>>>(dst, CNT, E, nbd,
                                feat, FT16, featN, nbf,
                                fc_w, w1_1, w2_1, w1_2, w2_2, W16);
    scan_kernel<<<1, 1024>>>(CNT, OFF, CUR, NORM, M);

    gemm16<false, false><<<grid, 256, smem>>>(FT16, nullptr, W16, nullptr,
                                              fc_b, nullptr, H16, M);

    fill_kernel<<<(E + 255) / 256, 256>>>(src, dst, CUR, CSR, E);

    agg_kernel<<<M, 128>>>(H16, NORM, OFF, CSR, F16);
    gemm16<true, false><<<grid, 256, smem>>>(F16, H16, W16 + 1 * D * D, W16 + 2 * D * D,
                                             b_1, nullptr, R16, M);

    agg_kernel<<<M, 128>>>(R16, NORM, OFF, CSR, F16);
    gemm16<true, true><<<grid, 256, smem>>>(F16, H16, W16 + 3 * D * D, W16 + 4 * D * D,
                                            b_2, out, nullptr, M);
}

// round 16
// speedup vs baseline: 1.0192x; 1.0192x over previous
#include <cuda_runtime.h>
#include <cuda_fp16.h>
#include <cstdint>
#include <math.h>

#define NMAX 20000
#define EMAX 320000
#define D 512

// ---------------- scratch (static device globals; no allocation) -------------
__device__ __half g_H16 [NMAX * D];
__device__ __half g_R16 [NMAX * D];
__device__ __half g_F16 [NMAX * D];
__device__ __half g_FT16[NMAX * D];      // feat in fp16
// fp16 weights [N][K]: fc, W1'(l1), W2'(l1), W1'(l2), W2'(l2)  (residual folded)
__device__ __half g_W16 [5 * D * D];
__device__ float  g_norm[NMAX];
__device__ int    g_cnt [NMAX];          // zero-init; scan re-zeroes each call
__device__ int    g_off [NMAX + 1];
__device__ int    g_cur [NMAX + 1];
__device__ int    g_csr [EMAX];

// ================= small helpers ==============================================
__device__ __forceinline__ void cp16(uint32_t dst, const void* src, int bytes)
{
    asm volatile("cp.async.cg.shared.global [%0], [%1], 16, %2;"
                 :: "r"(dst), "l"(src), "r"(bytes));
}
__device__ __forceinline__ void cp_commit() { asm volatile("cp.async.commit_group;"); }
template <int N> __device__ __forceinline__ void cp_wait()
{ asm volatile("cp.async.wait_group %0;" :: "n"(N)); }

__device__ __forceinline__ void mma16(float* c,
                                      unsigned a0, unsigned a1, unsigned a2, unsigned a3,
                                      unsigned b0, unsigned b1)
{
    asm volatile(
        "mma.sync.aligned.m16n8k16.row.col.f32.f16.f16.f32 "
        "{%0,%1,%2,%3},{%4,%5,%6,%7},{%8,%9},{%0,%1,%2,%3};"
        : "+f"(c[0]), "+f"(c[1]), "+f"(c[2]), "+f"(c[3])
        : "r"(a0), "r"(a1), "r"(a2), "r"(a3), "r"(b0), "r"(b1));
}

__device__ __forceinline__ void ldsm4(unsigned& r0, unsigned& r1, unsigned& r2, unsigned& r3,
                                      uint32_t addr)
{
    asm volatile("ldmatrix.sync.aligned.m8n8.x4.shared.b16 {%0,%1,%2,%3}, [%4];"
                 : "=r"(r0), "=r"(r1), "=r"(r2), "=r"(r3) : "r"(addr));
}

// ================= fused prep =================================================
// deg histogram | feat->fp16 | fcw->fp16 | layer weights: transpose + fold
// W1' = beta*W1 + (1-beta)*I ;  W2' = 0.1*(beta*W2 + (1-beta)*I)
__global__ __launch_bounds__(256)
void prep_all(const int* __restrict__ dst, int* __restrict__ cnt, int E, int nbd,
              const float* __restrict__ feat, __half* __restrict__ f16, int featN, int nbf,
              const float* __restrict__ fcw,
              const float* __restrict__ w11, const float* __restrict__ w21,
              const float* __restrict__ w12, const float* __restrict__ w22,
              __half* __restrict__ w16)
{
    __shared__ float tile[32][33];
    const int b = blockIdx.x, tid = threadIdx.x;

    if (b < nbd) {                                   // degree histogram
        int i = b * 256 + tid;
        if (i < E) atomicAdd(cnt + __ldg(dst + i), 1);
        return;
    }
    if (b < nbd + nbf) {                             // feat -> fp16
        int i = (b - nbd) * 2048 + tid * 8;
        if (i + 8 <= featN) {
            float4 a = *reinterpret_cast<const float4*>(feat + i);
            float4 c = *reinterpret_cast<const float4*>(feat + i + 4);
            __half2 h0 = __floats2half2_rn(a.x, a.y);
            __half2 h1 = __floats2half2_rn(a.z, a.w);
            __half2 h2 = __floats2half2_rn(c.x, c.y);
            __half2 h3 = __floats2half2_rn(c.z, c.w);
            uint4 o;
            o.x = *reinterpret_cast<uint32_t*>(&h0);
            o.y = *reinterpret_cast<uint32_t*>(&h1);
            o.z = *reinterpret_cast<uint32_t*>(&h2);
            o.w = *reinterpret_cast<uint32_t*>(&h3);
            *reinterpret_cast<uint4*>(f16 + i) = o;
        }
        return;
    }
    if (b < nbd + nbf + 128) {                       // fc_w -> fp16 (already [N][K])
        int i = (b - nbd - nbf) * 2048 + tid * 8;
        float4 a = *reinterpret_cast<const float4*>(fcw + i);
        float4 c = *reinterpret_cast<const float4*>(fcw + i + 4);
        __half2 h0 = __floats2half2_rn(a.x, a.y);
        __half2 h1 = __floats2half2_rn(a.z, a.w);
        __half2 h2 = __floats2half2_rn(c.x, c.y);
        __half2 h3 = __floats2half2_rn(c.z, c.w);
        uint4 o;
        o.x = *reinterpret_cast<uint32_t*>(&h0);
        o.y = *reinterpret_cast<uint32_t*>(&h1);
        o.z = *reinterpret_cast<uint32_t*>(&h2);
        o.w = *reinterpret_cast<uint32_t*>(&h3);
        *reinterpret_cast<uint4*>(w16 + i) = o;
        return;
    }
    // layer weights [K][N] -> [N][K] fp16, residual folded
    const float beta1 = 0.69314718056f;   // log(2)
    const float beta2 = 0.40546510811f;   // log(1.5)
    int b2  = b - nbd - nbf - 128;
    int mat = b2 >> 8;
    int rem = b2 & 255;
    int n0 = (rem & 15) * 32, k0 = (rem >> 4) * 32;
    int tx = tid & 31, ty = tid >> 5;
    const float* s;
    float bsc, idadd;
    if      (mat == 0) { s = w11; bsc = beta1;        idadd = 1.0f - beta1; }
    else if (mat == 1) { s = w21; bsc = 0.1f * beta1; idadd = 0.1f * (1.0f - beta1); }
    else if (mat == 2) { s = w12; bsc = beta2;        idadd = 1.0f - beta2; }
    else               { s = w22; bsc = 0.1f * beta2; idadd = 0.1f * (1.0f - beta2); }
    __half* dstw = w16 + (size_t)(mat + 1) * D * D;
    #pragma unroll
    for (int j = 0; j < 4; j++)
        tile[ty + j * 8][tx] = s[(size_t)(k0 + ty + j * 8) * D + n0 + tx];
    __syncthreads();
    #pragma unroll
    for (int j = 0; j < 4; j++) {
        int nn = n0 + ty + j * 8;
        int kk = k0 + tx;
        float v = tile[tx][ty + j * 8] * bsc + ((nn == kk) ? idadd : 0.0f);
        dstw[(size_t)nn * D + kk] = __float2half(v);
    }
}

// ================= scan: warp-shuffle prefix + cur + norm + cnt re-zero =======
__global__ void scan_kernel(int* __restrict__ cnt, int* __restrict__ off,
                            int* __restrict__ cur, float* __restrict__ norm, int n)
{
    __shared__ int sh[32];
    const int CH = 20;
    int t = threadIdx.x;
    int lane = t & 31, wid = t >> 5;
    int base = t * CH;
    int v[CH];
    if (base + CH <= n) {
        #pragma unroll
        for (int i = 0; i < CH / 4; i++) {
            int4 q = *reinterpret_cast<const int4*>(cnt + base + i * 4);
            v[i * 4 + 0] = q.x; v[i * 4 + 1] = q.y;
            v[i * 4 + 2] = q.z; v[i * 4 + 3] = q.w;
        }
    } else {
        #pragma unroll
        for (int i = 0; i < CH; i++) v[i] = (base + i < n) ? cnt[base + i] : 0;
    }
    int s = 0;
    #pragma unroll
    for (int i = 0; i < CH; i++) s += v[i];

    // warp inclusive scan
    int incl = s;
    #pragma unroll
    for (int d = 1; d < 32; d <<= 1) {
        int x = __shfl_up_sync(0xFFFFFFFFu, incl, d);
        if (lane >= d) incl += x;
    }
    if (lane == 31) sh[wid] = incl;
    __syncthreads();
    if (wid == 0) {
        int w = sh[lane];
        int wincl = w;
        #pragma unroll
        for (int d = 1; d < 32; d <<= 1) {
            int x = __shfl_up_sync(0xFFFFFFFFu, wincl, d);
            if (lane >= d) wincl += x;
        }
        sh[lane] = wincl - w;    // exclusive warp prefix
    }
    __syncthreads();
    int run = sh[wid] + incl - s;    // exclusive prefix for this thread

    int offv[CH];
    float nv[CH];
    #pragma unroll
    for (int i = 0; i < CH; i++) {
        offv[i] = run;
        nv[i]   = rsqrtf(fmaxf((float)v[i], 1.0f));
        run += v[i];
    }
    if (base + CH <= n) {
        #pragma unroll
        for (int i = 0; i < CH; i += 4) {
            int4 o = make_int4(offv[i], offv[i + 1], offv[i + 2], offv[i + 3]);
            *reinterpret_cast<int4*>(off + base + i) = o;
            *reinterpret_cast<int4*>(cur + base + i) = o;
            *reinterpret_cast<float4*>(norm + base + i) =
                make_float4(nv[i], nv[i + 1], nv[i + 2], nv[i + 3]);
            *reinterpret_cast<int4*>(cnt + base + i) = make_int4(0, 0, 0, 0);
        }
    } else {
        for (int i = 0; i < CH; i++) {
            int idx = base + i;
            if (idx < n) {
                off[idx] = offv[i]; cur[idx] = offv[i]; norm[idx] = nv[i];
                cnt[idx] = 0;
            }
        }
    }
    if (t == 1023) off[n] = run;
}

__global__ void fill_kernel(const int* __restrict__ src, const int* __restrict__ dst,
                            int* __restrict__ cur, int* __restrict__ csr, int E)
{
    int i = blockIdx.x * blockDim.x + threadIdx.x;
    if (i < E) {
        int d = __ldg(dst + i);
        int p = atomicAdd(cur + d, 1);
        csr[p] = __ldg(src + i);
    }
}

// ================= aggregation: fp16 gather -> fp16 out ======================
__global__ __launch_bounds__(128)
void agg_kernel(const __half* __restrict__ h, const float* __restrict__ norm,
                const int* __restrict__ off, const int* __restrict__ csr,
                __half* __restrict__ F)
{
    int node = blockIdx.x;
    int c    = threadIdx.x * 4;
    int s0 = __ldg(off + node);
    int s1 = __ldg(off + node + 1);
    float4 acc = make_float4(0.f, 0.f, 0.f, 0.f);
    int j = s0;
    for (; j + 3 < s1; j += 4) {
        int   si[4];
        float wi[4];
        #pragma unroll
        for (int u = 0; u < 4; u++) si[u] = __ldg(csr + j + u);
        #pragma unroll
        for (int u = 0; u < 4; u++) wi[u] = __ldg(norm + si[u]);
        uint2 q[4];
        #pragma unroll
        for (int u = 0; u < 4; u++)
            q[u] = *reinterpret_cast<const uint2*>(h + (size_t)si[u] * D + c);
        #pragma unroll
        for (int u = 0; u < 4; u++) {
            float2 lo = __half22float2(*reinterpret_cast<__half2*>(&q[u].x));
            float2 hi = __half22float2(*reinterpret_cast<__half2*>(&q[u].y));
            acc.x += wi[u] * lo.x;
            acc.y += wi[u] * lo.y;
            acc.z += wi[u] * hi.x;
            acc.w += wi[u] * hi.y;
        }
    }
    for (; j < s1; j++) {
        int sA = __ldg(csr + j);
        float wA = __ldg(norm + sA);
        uint2 q = *reinterpret_cast<const uint2*>(h + (size_t)sA * D + c);
        float2 lo = __half22float2(*reinterpret_cast<__half2*>(&q.x));
        float2 hi = __half22float2(*reinterpret_cast<__half2*>(&q.y));
        acc.x += wA * lo.x; acc.y += wA * lo.y;
        acc.z += wA * hi.x; acc.w += wA * hi.y;
    }
    float wn = __ldg(norm + node) * 0.9f;
    __half2 lo = __floats2half2_rn(acc.x * wn, acc.y * wn);
    __half2 hi = __floats2half2_rn(acc.z * wn, acc.w * wn);
    uint2 o;
    o.x = *reinterpret_cast<uint32_t*>(&lo);
    o.y = *reinterpret_cast<uint32_t*>(&hi);
    *reinterpret_cast<uint2*>(F + (size_t)node * D + c) = o;
}

// ================= unified fp16 GEMM (cp.async + ldmatrix, m16n8k16) =========
// CTA tile 128 x 128; SMEM rows stride 80 B; 4-stage pipeline.
#define STG 4
#define TB16 10240

// LAYER=false: out16 = half(A0@B0^T + bias)                (T=16)
// LAYER=true:  out = relu(A0@B0' + A1@B1' + bias)          (T=32, weights folded)
template <bool LAYER, bool OUT32>
__global__ __launch_bounds__(256, 2)
void gemm16(const __half* __restrict__ A0, const __half* __restrict__ A1,
            const __half* __restrict__ B0, const __half* __restrict__ B1,
            const float* __restrict__ bias, float* __restrict__ C,
            __half* __restrict__ C16, int M)
{
    extern __shared__ unsigned sm[];
    const int tid = threadIdx.x, lane = tid & 31, warp = tid >> 5;
    const int wm = warp >> 2, wn = warp & 3;
    const int bm = blockIdx.y * 128, bn = blockIdx.x * 128;
    const uint32_t smb  = (uint32_t)__cvta_generic_to_shared(sm);
    const uint32_t smbB = smb + STG * TB16;

    float acc[4][4][4] = {};

    int lrow[2], lch[2], avalid[2];
    uint32_t dA[2], dB[2];
    #pragma unroll
    for (int i = 0; i < 2; i++) {
        int cid = tid + i * 256;
        lrow[i] = cid >> 2;
        lch[i]  = cid & 3;
        dA[i] = smb  + (uint32_t)(lrow[i] * 80 + lch[i] * 16);
        dB[i] = smbB + (uint32_t)(lrow[i] * 80 + lch[i] * 16);
        avalid[i] = (bm + lrow[i] < M) ? 16 : 0;
    }

    auto issue = [&](int stage, int t) {
        const __half* Ap;
        const __half* Bp;
        int k0;
        if (LAYER) {
            bool second = (t >= 16);
            Ap = second ? A1 : A0;
            Bp = second ? B1 : B0;
            k0 = (t & 15) * 32;
        } else {
            Ap = A0; Bp = B0; k0 = t * 32;
        }
        uint32_t so = (uint32_t)stage * TB16;
        #pragma unroll
        for (int i = 0; i < 2; i++) {
            const __half* as = Ap + (size_t)(avalid[i] ? bm + lrow[i] : 0) * D + k0 + lch[i] * 8;
            cp16(dA[i] + so, as, avalid[i]);
            const __half* bs = Bp + (size_t)(bn + lrow[i]) * D + k0 + lch[i] * 8;
            cp16(dB[i] + so, bs, 16);
        }
        cp_commit();
    };

    uint32_t aoff[4];
    #pragma unroll
    for (int mt = 0; mt < 4; mt++) {
        int row = wm * 64 + mt * 16 + (lane & 15);
        aoff[mt] = (uint32_t)(row * 80 + ((lane >> 4) & 1) * 16);
    }
    uint32_t boff[2];
    #pragma unroll
    for (int np = 0; np < 2; np++) {
        int row = wn * 32 + np * 16 + (lane & 7) + ((lane & 16) ? 8 : 0);
        boff[np] = (uint32_t)(row * 80 + ((lane >> 3) & 1) * 16);
    }

    auto compute = [&](int stage) {
        uint32_t sa = smb  + (uint32_t)stage * TB16;
        uint32_t sb = smbB + (uint32_t)stage * TB16;
        #pragma unroll
        for (int kc = 0; kc < 2; kc++) {
            unsigned af[4][4], bf[4][2];
            #pragma unroll
            for (int mt = 0; mt < 4; mt++)
                ldsm4(af[mt][0], af[mt][1], af[mt][2], af[mt][3],
                      sa + aoff[mt] + kc * 32);
            #pragma unroll
            for (int np = 0; np < 2; np++)
                ldsm4(bf[2 * np][0], bf[2 * np][1], bf[2 * np + 1][0], bf[2 * np + 1][1],
                      sb + boff[np] + kc * 32);
            #pragma unroll
            for (int mt = 0; mt < 4; mt++)
                #pragma unroll
                for (int nt = 0; nt < 4; nt++)
                    mma16(acc[mt][nt], af[mt][0], af[mt][1], af[mt][2], af[mt][3],
                          bf[nt][0], bf[nt][1]);
        }
    };

    const int T = LAYER ? 32 : 16;
    #pragma unroll
    for (int p = 0; p < STG - 1; p++) issue(p, p);
    for (int t = 0; t < T; t++) {
        cp_wait<STG - 2>();
        __syncthreads();
        if (t + STG - 1 < T) issue((t + STG - 1) % STG, t + STG - 1);
        else                 cp_commit();
        compute(t % STG);
    }

    const int grp = lane >> 2, tig = lane & 3;
    #pragma unroll
    for (int mt = 0; mt < 4; mt++) {
        int gr[2];
        gr[0] = bm + wm * 64 + mt * 16 + grp;
        gr[1] = gr[0] + 8;
        #pragma unroll
        for (int nt = 0; nt < 4; nt++) {
            int gc = bn + wn * 32 + nt * 8 + tig * 2;
            float2 bb = *reinterpret_cast<const float2*>(bias + gc);
            #pragma unroll
            for (int hh = 0; hh < 2; hh++) {
                if (gr[hh] >= M) continue;
                size_t base = (size_t)gr[hh] * D + gc;
                float2 v;
                v.x = acc[mt][nt][2 * hh + 0] + bb.x;
                v.y = acc[mt][nt][2 * hh + 1] + bb.y;
                if (LAYER) {
                    v.x = fmaxf(v.x, 0.f);
                    v.y = fmaxf(v.y, 0.f);
                }
                if (OUT32)
                    *reinterpret_cast<float2*>(C + base) = v;
                else
                    *reinterpret_cast<__half2*>(C16 + base) = __floats2half2_rn(v.x, v.y);
            }
        }
    }
}

// ================= host orchestration =========================================
extern "C" void kernel_launch(void* const* d_in, const int* in_sizes, int n_in,
                              void* d_out, int out_size)
{
    const float* feat = (const float*)d_in[0];
    const int*   src  = (const int*)  d_in[1];
    const int*   dst  = (const int*)  d_in[2];
    const float* fc_w = (const float*)d_in[3];
    const float* fc_b = (const float*)d_in[4];
    const float* w1_1 = (const float*)d_in[5];
    const float* w2_1 = (const float*)d_in[6];
    const float* b_1  = (const float*)d_in[7];
    const float* w1_2 = (const float*)d_in[8];
    const float* w2_2 = (const float*)d_in[9];
    const float* b_2  = (const float*)d_in[10];
    float* out = (float*)d_out;

    int M = in_sizes[0] / D;
    int E = in_sizes[1];

    float *NORM;
    __half *H16, *R16, *F16, *FT16, *W16;
    int *CNT, *OFF, *CUR, *CSR;
    cudaGetSymbolAddress((void**)&H16,  g_H16);
    cudaGetSymbolAddress((void**)&R16,  g_R16);
    cudaGetSymbolAddress((void**)&F16,  g_F16);
    cudaGetSymbolAddress((void**)&FT16, g_FT16);
    cudaGetSymbolAddress((void**)&W16,  g_W16);
    cudaGetSymbolAddress((void**)&NORM, g_norm);
    cudaGetSymbolAddress((void**)&CNT,  g_cnt);
    cudaGetSymbolAddress((void**)&OFF,  g_off);
    cudaGetSymbolAddress((void**)&CUR,  g_cur);
    cudaGetSymbolAddress((void**)&CSR,  g_csr);

    const int smem = STG * TB16 * 2;       // 81920
    cudaFuncSetAttribute((const void*)gemm16<false, false>, cudaFuncAttributeMaxDynamicSharedMemorySize, smem);
    cudaFuncSetAttribute((const void*)gemm16<true,  false>, cudaFuncAttributeMaxDynamicSharedMemorySize, smem);
    cudaFuncSetAttribute((const void*)gemm16<true,  true >, cudaFuncAttributeMaxDynamicSharedMemorySize, smem);

    dim3 grid(D / 128, (M + 127) / 128);

    int featN = M * D;
    int nbd = (E + 255) / 256;
    int nbf = (featN + 2047) / 2048;
    int nb_total = nbd + nbf + 128 + 1024;

    prep_all<<<nb_total, 256>>>(dst, CNT, E, nbd,
                                feat, FT16, featN, nbf,
                                fc_w, w1_1, w2_1, w1_2, w2_2, W16);
    scan_kernel<<<1, 1024>>>(CNT, OFF, CUR, NORM, M);

    gemm16<false, false><<<grid, 256, smem>>>(FT16, nullptr, W16, nullptr,
                                              fc_b, nullptr, H16, M);

    fill_kernel<<<(E + 255) / 256, 256>>>(src, dst, CUR, CSR, E);

    agg_kernel<<<M, 128>>>(H16, NORM, OFF, CSR, F16);
    gemm16<true, false><<<grid, 256, smem>>>(F16, H16, W16 + 1 * D * D, W16 + 2 * D * D,
                                             b_1, nullptr, R16, M);

    agg_kernel<<<M, 128>>>(R16, NORM, OFF, CSR, F16);
    gemm16<true, true><<<grid, 256, smem>>>(F16, H16, W16 + 3 * D * D, W16 + 4 * D * D,
                                            b_2, out, nullptr, M);
}

// round 17
// speedup vs baseline: 1.2344x; 1.2111x over previous
#include <cuda_runtime.h>
#include <cuda_fp16.h>
#include <cstdint>
#include <math.h>

#define NMAX 20000
#define EMAX 320000
#define D 512

// ---------------- scratch (static device globals; no allocation) -------------
__device__ __half g_H16 [NMAX * D];
__device__ __half g_R16 [NMAX * D];
__device__ __half g_F16 [NMAX * D];
__device__ __half g_FT16[NMAX * D];      // feat in fp16
// fp16 weights [N][K]: fc, W1'(l1), W2'(l1), W1'(l2), W2'(l2)  (residual folded)
__device__ __half g_W16 [5 * D * D];
__device__ float  g_norm[NMAX];
__device__ int    g_cnt [NMAX];          // zero-init; scan re-zeroes each call
__device__ int    g_off [NMAX + 1];
__device__ int    g_cur [NMAX + 1];
__device__ int    g_csr [EMAX];

// ================= small helpers ==============================================
__device__ __forceinline__ void cp16(uint32_t dst, const void* src, int bytes)
{
    asm volatile("cp.async.cg.shared.global [%0], [%1], 16, %2;"
                 :: "r"(dst), "l"(src), "r"(bytes));
}
__device__ __forceinline__ void cp_commit() { asm volatile("cp.async.commit_group;"); }
template <int N> __device__ __forceinline__ void cp_wait()
{ asm volatile("cp.async.wait_group %0;" :: "n"(N)); }

__device__ __forceinline__ void mma16(float* c,
                                      unsigned a0, unsigned a1, unsigned a2, unsigned a3,
                                      unsigned b0, unsigned b1)
{
    asm volatile(
        "mma.sync.aligned.m16n8k16.row.col.f32.f16.f16.f32 "
        "{%0,%1,%2,%3},{%4,%5,%6,%7},{%8,%9},{%0,%1,%2,%3};"
        : "+f"(c[0]), "+f"(c[1]), "+f"(c[2]), "+f"(c[3])
        : "r"(a0), "r"(a1), "r"(a2), "r"(a3), "r"(b0), "r"(b1));
}

__device__ __forceinline__ void ldsm4(unsigned& r0, unsigned& r1, unsigned& r2, unsigned& r3,
                                      uint32_t addr)
{
    asm volatile("ldmatrix.sync.aligned.m8n8.x4.shared.b16 {%0,%1,%2,%3}, [%4];"
                 : "=r"(r0), "=r"(r1), "=r"(r2), "=r"(r3) : "r"(addr));
}

// ================= fused prep =================================================
__global__ __launch_bounds__(256)
void prep_all(const int* __restrict__ dst, int* __restrict__ cnt, int E, int nbd,
              const float* __restrict__ feat, __half* __restrict__ f16, int featN, int nbf,
              const float* __restrict__ fcw,
              const float* __restrict__ w11, const float* __restrict__ w21,
              const float* __restrict__ w12, const float* __restrict__ w22,
              __half* __restrict__ w16)
{
    __shared__ float tile[32][33];
    const int b = blockIdx.x, tid = threadIdx.x;

    if (b < nbd) {                                   // degree histogram
        int i = b * 256 + tid;
        if (i < E) atomicAdd(cnt + __ldg(dst + i), 1);
        return;
    }
    if (b < nbd + nbf) {                             // feat -> fp16
        int i = (b - nbd) * 2048 + tid * 8;
        if (i + 8 <= featN) {
            float4 a = *reinterpret_cast<const float4*>(feat + i);
            float4 c = *reinterpret_cast<const float4*>(feat + i + 4);
            __half2 h0 = __floats2half2_rn(a.x, a.y);
            __half2 h1 = __floats2half2_rn(a.z, a.w);
            __half2 h2 = __floats2half2_rn(c.x, c.y);
            __half2 h3 = __floats2half2_rn(c.z, c.w);
            uint4 o;
            o.x = *reinterpret_cast<uint32_t*>(&h0);
            o.y = *reinterpret_cast<uint32_t*>(&h1);
            o.z = *reinterpret_cast<uint32_t*>(&h2);
            o.w = *reinterpret_cast<uint32_t*>(&h3);
            *reinterpret_cast<uint4*>(f16 + i) = o;
        }
        return;
    }
    if (b < nbd + nbf + 128) {                       // fc_w -> fp16 (already [N][K])
        int i = (b - nbd - nbf) * 2048 + tid * 8;
        float4 a = *reinterpret_cast<const float4*>(fcw + i);
        float4 c = *reinterpret_cast<const float4*>(fcw + i + 4);
        __half2 h0 = __floats2half2_rn(a.x, a.y);
        __half2 h1 = __floats2half2_rn(a.z, a.w);
        __half2 h2 = __floats2half2_rn(c.x, c.y);
        __half2 h3 = __floats2half2_rn(c.z, c.w);
        uint4 o;
        o.x = *reinterpret_cast<uint32_t*>(&h0);
        o.y = *reinterpret_cast<uint32_t*>(&h1);
        o.z = *reinterpret_cast<uint32_t*>(&h2);
        o.w = *reinterpret_cast<uint32_t*>(&h3);
        *reinterpret_cast<uint4*>(w16 + i) = o;
        return;
    }
    // layer weights [K][N] -> [N][K] fp16, residual folded
    const float beta1 = 0.69314718056f;   // log(2)
    const float beta2 = 0.40546510811f;   // log(1.5)
    int b2  = b - nbd - nbf - 128;
    int mat = b2 >> 8;
    int rem = b2 & 255;
    int n0 = (rem & 15) * 32, k0 = (rem >> 4) * 32;
    int tx = tid & 31, ty = tid >> 5;
    const float* s;
    float bsc, idadd;
    if      (mat == 0) { s = w11; bsc = beta1;        idadd = 1.0f - beta1; }
    else if (mat == 1) { s = w21; bsc = 0.1f * beta1; idadd = 0.1f * (1.0f - beta1); }
    else if (mat == 2) { s = w12; bsc = beta2;        idadd = 1.0f - beta2; }
    else               { s = w22; bsc = 0.1f * beta2; idadd = 0.1f * (1.0f - beta2); }
    __half* dstw = w16 + (size_t)(mat + 1) * D * D;
    #pragma unroll
    for (int j = 0; j < 4; j++)
        tile[ty + j * 8][tx] = s[(size_t)(k0 + ty + j * 8) * D + n0 + tx];
    __syncthreads();
    #pragma unroll
    for (int j = 0; j < 4; j++) {
        int nn = n0 + ty + j * 8;
        int kk = k0 + tx;
        float v = tile[tx][ty + j * 8] * bsc + ((nn == kk) ? idadd : 0.0f);
        dstw[(size_t)nn * D + kk] = __float2half(v);
    }
}

// ================= scan: warp-shuffle prefix + cur + norm + cnt re-zero =======
__global__ void scan_kernel(int* __restrict__ cnt, int* __restrict__ off,
                            int* __restrict__ cur, float* __restrict__ norm, int n)
{
    __shared__ int sh[32];
    const int CH = 20;
    int t = threadIdx.x;
    int lane = t & 31, wid = t >> 5;
    int base = t * CH;
    int v[CH];
    if (base + CH <= n) {
        #pragma unroll
        for (int i = 0; i < CH / 4; i++) {
            int4 q = *reinterpret_cast<const int4*>(cnt + base + i * 4);
            v[i * 4 + 0] = q.x; v[i * 4 + 1] = q.y;
            v[i * 4 + 2] = q.z; v[i * 4 + 3] = q.w;
        }
    } else {
        #pragma unroll
        for (int i = 0; i < CH; i++) v[i] = (base + i < n) ? cnt[base + i] : 0;
    }
    int s = 0;
    #pragma unroll
    for (int i = 0; i < CH; i++) s += v[i];

    int incl = s;
    #pragma unroll
    for (int d = 1; d < 32; d <<= 1) {
        int x = __shfl_up_sync(0xFFFFFFFFu, incl, d);
        if (lane >= d) incl += x;
    }
    if (lane == 31) sh[wid] = incl;
    __syncthreads();
    if (wid == 0) {
        int w = sh[lane];
        int wincl = w;
        #pragma unroll
        for (int d = 1; d < 32; d <<= 1) {
            int x = __shfl_up_sync(0xFFFFFFFFu, wincl, d);
            if (lane >= d) wincl += x;
        }
        sh[lane] = wincl - w;
    }
    __syncthreads();
    int run = sh[wid] + incl - s;

    int offv[CH];
    float nv[CH];
    #pragma unroll
    for (int i = 0; i < CH; i++) {
        offv[i] = run;
        nv[i]   = rsqrtf(fmaxf((float)v[i], 1.0f));
        run += v[i];
    }
    if (base + CH <= n) {
        #pragma unroll
        for (int i = 0; i < CH; i += 4) {
            int4 o = make_int4(offv[i], offv[i + 1], offv[i + 2], offv[i + 3]);
            *reinterpret_cast<int4*>(off + base + i) = o;
            *reinterpret_cast<int4*>(cur + base + i) = o;
            *reinterpret_cast<float4*>(norm + base + i) =
                make_float4(nv[i], nv[i + 1], nv[i + 2], nv[i + 3]);
            *reinterpret_cast<int4*>(cnt + base + i) = make_int4(0, 0, 0, 0);
        }
    } else {
        for (int i = 0; i < CH; i++) {
            int idx = base + i;
            if (idx < n) {
                off[idx] = offv[i]; cur[idx] = offv[i]; norm[idx] = nv[i];
                cnt[idx] = 0;
            }
        }
    }
    if (t == 1023) off[n] = run;
}

// ================= aggregation: fp16 gather -> fp16 out ======================
__global__ __launch_bounds__(128)
void agg_kernel(const __half* __restrict__ h, const float* __restrict__ norm,
                const int* __restrict__ off, const int* __restrict__ csr,
                __half* __restrict__ F)
{
    int node = blockIdx.x;
    int c    = threadIdx.x * 4;
    int s0 = __ldg(off + node);
    int s1 = __ldg(off + node + 1);
    float4 acc = make_float4(0.f, 0.f, 0.f, 0.f);
    int j = s0;
    for (; j + 3 < s1; j += 4) {
        int   si[4];
        float wi[4];
        #pragma unroll
        for (int u = 0; u < 4; u++) si[u] = __ldg(csr + j + u);
        #pragma unroll
        for (int u = 0; u < 4; u++) wi[u] = __ldg(norm + si[u]);
        uint2 q[4];
        #pragma unroll
        for (int u = 0; u < 4; u++)
            q[u] = *reinterpret_cast<const uint2*>(h + (size_t)si[u] * D + c);
        #pragma unroll
        for (int u = 0; u < 4; u++) {
            float2 lo = __half22float2(*reinterpret_cast<__half2*>(&q[u].x));
            float2 hi = __half22float2(*reinterpret_cast<__half2*>(&q[u].y));
            acc.x += wi[u] * lo.x;
            acc.y += wi[u] * lo.y;
            acc.z += wi[u] * hi.x;
            acc.w += wi[u] * hi.y;
        }
    }
    for (; j < s1; j++) {
        int sA = __ldg(csr + j);
        float wA = __ldg(norm + sA);
        uint2 q = *reinterpret_cast<const uint2*>(h + (size_t)sA * D + c);
        float2 lo = __half22float2(*reinterpret_cast<__half2*>(&q.x));
        float2 hi = __half22float2(*reinterpret_cast<__half2*>(&q.y));
        acc.x += wA * lo.x; acc.y += wA * lo.y;
        acc.z += wA * hi.x; acc.w += wA * hi.y;
    }
    float wn = __ldg(norm + node) * 0.9f;
    __half2 lo = __floats2half2_rn(acc.x * wn, acc.y * wn);
    __half2 hi = __floats2half2_rn(acc.z * wn, acc.w * wn);
    uint2 o;
    o.x = *reinterpret_cast<uint32_t*>(&lo);
    o.y = *reinterpret_cast<uint32_t*>(&hi);
    *reinterpret_cast<uint2*>(F + (size_t)node * D + c) = o;
}

// ================= unified fp16 GEMM (cp.async + ldmatrix, m16n8k16) =========
// CTA tile 128 x 128, K-chunk 64. SMEM rows: 64 halves = 128 B exactly,
// 16B-chunk swizzle c' = c ^ (row & 7). 3-stage pipeline.
#define STG 3
#define TS16 16384        // bytes per operand tile per stage (128 x 128B)

// LAYER=false: out16 = half(A0@B0^T + bias); extra blocks run CSR fill (T=8)
// LAYER=true:  out = relu(A0@B0' + A1@B1' + bias)                       (T=16)
template <bool LAYER, bool OUT32>
__global__ __launch_bounds__(256, 2)
void gemm16(const __half* __restrict__ A0, const __half* __restrict__ A1,
            const __half* __restrict__ B0, const __half* __restrict__ B1,
            const float* __restrict__ bias, float* __restrict__ C,
            __half* __restrict__ C16, int M, int nGemm,
            const int* __restrict__ src, const int* __restrict__ dst,
            int* __restrict__ cur, int* __restrict__ csr, int E)
{
    const int tid = threadIdx.x;

    // ---- fused CSR fill blocks (fc launch only) -----------------------------
    if (!LAYER && (int)blockIdx.x >= nGemm) {
        int i = ((int)blockIdx.x - nGemm) * 256 + tid;
        if (i < E) {
            int d = __ldg(dst + i);
            int p = atomicAdd(cur + d, 1);
            csr[p] = __ldg(src + i);
        }
        return;
    }

    extern __shared__ unsigned sm[];
    const int lane = tid & 31, warp = tid >> 5;
    const int wm = warp >> 2, wn = warp & 3;
    const int bx = (int)blockIdx.x & 3, by = (int)blockIdx.x >> 2;
    const int bm = by * 128, bn = bx * 128;
    const uint32_t smb  = (uint32_t)__cvta_generic_to_shared(sm);
    const uint32_t smbB = smb + STG * TS16;

    float acc[4][4][4] = {};

    // loaders: 1024 chunks/tile per operand, 4/thread each
    int lrow[4], lch[4], avalid[4];
    uint32_t dA[4], dB[4];
    #pragma unroll
    for (int i = 0; i < 4; i++) {
        int cid = tid + i * 256;
        lrow[i] = cid >> 3;
        lch[i]  = cid & 7;
        uint32_t o = (uint32_t)(lrow[i] * 128 + ((lch[i] ^ (lrow[i] & 7)) << 4));
        dA[i] = smb  + o;
        dB[i] = smbB + o;
        avalid[i] = (bm + lrow[i] < M) ? 16 : 0;
    }

    auto issue = [&](int stage, int t) {
        const __half* Ap;
        const __half* Bp;
        int k0;
        if (LAYER) {
            bool second = (t >= 8);
            Ap = second ? A1 : A0;
            Bp = second ? B1 : B0;
            k0 = (t & 7) * 64;
        } else {
            Ap = A0; Bp = B0; k0 = t * 64;
        }
        uint32_t so = (uint32_t)stage * TS16;
        #pragma unroll
        for (int i = 0; i < 4; i++) {
            const __half* as = Ap + (size_t)(avalid[i] ? bm + lrow[i] : 0) * D + k0 + lch[i] * 8;
            cp16(dA[i] + so, as, avalid[i]);
            const __half* bs = Bp + (size_t)(bn + lrow[i]) * D + k0 + lch[i] * 8;
            cp16(dB[i] + so, bs, 16);
        }
        cp_commit();
    };

    // ldmatrix lane bases (per-lane row -> per-lane XOR key)
    const int hiA = (lane >> 4) & 1;
    uint32_t abase[4];
    int akey[4];
    #pragma unroll
    for (int mt = 0; mt < 4; mt++) {
        int row = wm * 64 + mt * 16 + (lane & 15);
        akey[mt]  = row & 7;
        abase[mt] = (uint32_t)row * 128u;
    }
    const int hiB = (lane >> 3) & 1;
    uint32_t bbase[2];
    int bkey[2];
    #pragma unroll
    for (int np = 0; np < 2; np++) {
        int row = wn * 32 + np * 16 + (lane & 7) + ((lane & 16) ? 8 : 0);
        bkey[np]  = row & 7;
        bbase[np] = (uint32_t)row * 128u;
    }

    auto compute = [&](int stage) {
        uint32_t sa = smb  + (uint32_t)stage * TS16;
        uint32_t sb = smbB + (uint32_t)stage * TS16;
        #pragma unroll
        for (int kc = 0; kc < 4; kc++) {
            unsigned af[4][4], bf[4][2];
            #pragma unroll
            for (int mt = 0; mt < 4; mt++)
                ldsm4(af[mt][0], af[mt][1], af[mt][2], af[mt][3],
                      sa + abase[mt] + (uint32_t)(((2 * kc + hiA) ^ akey[mt]) << 4));
            #pragma unroll
            for (int np = 0; np < 2; np++)
                ldsm4(bf[2 * np][0], bf[2 * np][1], bf[2 * np + 1][0], bf[2 * np + 1][1],
                      sb + bbase[np] + (uint32_t)(((2 * kc + hiB) ^ bkey[np]) << 4));
            #pragma unroll
            for (int mt = 0; mt < 4; mt++)
                #pragma unroll
                for (int nt = 0; nt < 4; nt++)
                    mma16(acc[mt][nt], af[mt][0], af[mt][1], af[mt][2], af[mt][3],
                          bf[nt][0], bf[nt][1]);
        }
    };

    const int T = LAYER ? 16 : 8;
    issue(0, 0);
    issue(1, 1);
    for (int t = 0; t < T; t++) {
        cp_wait<STG - 2>();
        __syncthreads();
        if (t + STG - 1 < T) issue((t + STG - 1) % STG, t + STG - 1);
        else                 cp_commit();
        compute(t % STG);
    }

    const int grp = lane >> 2, tig = lane & 3;
    #pragma unroll
    for (int mt = 0; mt < 4; mt++) {
        int gr[2];
        gr[0] = bm + wm * 64 + mt * 16 + grp;
        gr[1] = gr[0] + 8;
        #pragma unroll
        for (int nt = 0; nt < 4; nt++) {
            int gc = bn + wn * 32 + nt * 8 + tig * 2;
            float2 bb = *reinterpret_cast<const float2*>(bias + gc);
            #pragma unroll
            for (int hh = 0; hh < 2; hh++) {
                if (gr[hh] >= M) continue;
                size_t base = (size_t)gr[hh] * D + gc;
                float2 v;
                v.x = acc[mt][nt][2 * hh + 0] + bb.x;
                v.y = acc[mt][nt][2 * hh + 1] + bb.y;
                if (LAYER) {
                    v.x = fmaxf(v.x, 0.f);
                    v.y = fmaxf(v.y, 0.f);
                }
                if (OUT32)
                    *reinterpret_cast<float2*>(C + base) = v;
                else
                    *reinterpret_cast<__half2*>(C16 + base) = __floats2half2_rn(v.x, v.y);
            }
        }
    }
}

// ================= host orchestration =========================================
extern "C" void kernel_launch(void* const* d_in, const int* in_sizes, int n_in,
                              void* d_out, int out_size)
{
    const float* feat = (const float*)d_in[0];
    const int*   src  = (const int*)  d_in[1];
    const int*   dst  = (const int*)  d_in[2];
    const float* fc_w = (const float*)d_in[3];
    const float* fc_b = (const float*)d_in[4];
    const float* w1_1 = (const float*)d_in[5];
    const float* w2_1 = (const float*)d_in[6];
    const float* b_1  = (const float*)d_in[7];
    const float* w1_2 = (const float*)d_in[8];
    const float* w2_2 = (const float*)d_in[9];
    const float* b_2  = (const float*)d_in[10];
    float* out = (float*)d_out;

    int M = in_sizes[0] / D;
    int E = in_sizes[1];

    float *NORM;
    __half *H16, *R16, *F16, *FT16, *W16;
    int *CNT, *OFF, *CUR, *CSR;
    cudaGetSymbolAddress((void**)&H16,  g_H16);
    cudaGetSymbolAddress((void**)&R16,  g_R16);
    cudaGetSymbolAddress((void**)&F16,  g_F16);
    cudaGetSymbolAddress((void**)&FT16, g_FT16);
    cudaGetSymbolAddress((void**)&W16,  g_W16);
    cudaGetSymbolAddress((void**)&NORM, g_norm);
    cudaGetSymbolAddress((void**)&CNT,  g_cnt);
    cudaGetSymbolAddress((void**)&OFF,  g_off);
    cudaGetSymbolAddress((void**)&CUR,  g_cur);
    cudaGetSymbolAddress((void**)&CSR,  g_csr);

    const int smem = STG * TS16 * 2;       // 98304
    cudaFuncSetAttribute((const void*)gemm16<false, false>, cudaFuncAttributeMaxDynamicSharedMemorySize, smem);
    cudaFuncSetAttribute((const void*)gemm16<true,  false>, cudaFuncAttributeMaxDynamicSharedMemorySize, smem);
    cudaFuncSetAttribute((const void*)gemm16<true,  true >, cudaFuncAttributeMaxDynamicSharedMemorySize, smem);

    const int nGemm = (D / 128) * ((M + 127) / 128);   // 628 for M=20000
    const int nFill = (E + 255) / 256;

    int featN = M * D;
    int nbd = (E + 255) / 256;
    int nbf = (featN + 2047) / 2048;
    int nb_total = nbd + nbf + 128 + 1024;

    prep_all<<<nb_total, 256>>>(dst, CNT, E, nbd,
                                feat, FT16, featN, nbf,
                                fc_w, w1_1, w2_1, w1_2, w2_2, W16);
    scan_kernel<<<1, 1024>>>(CNT, OFF, CUR, NORM, M);

    // fc GEMM + fused CSR fill (extra blocks)
    gemm16<false, false><<<nGemm + nFill, 256, smem>>>(
        FT16, nullptr, W16, nullptr, fc_b, nullptr, H16, M,
        nGemm, src, dst, CUR, CSR, E);

    agg_kernel<<<M, 128>>>(H16, NORM, OFF, CSR, F16);
    gemm16<true, false><<<nGemm, 256, smem>>>(
        F16, H16, W16 + 1 * D * D, W16 + 2 * D * D, b_1, nullptr, R16, M,
        nGemm, nullptr, nullptr, nullptr, nullptr, 0);

    agg_kernel<<<M, 128>>>(R16, NORM, OFF, CSR, F16);
    gemm16<true, true><<<nGemm, 256, smem>>>(
        F16, H16, W16 + 3 * D * D, W16 + 4 * D * D, b_2, out, nullptr, M,
        nGemm, nullptr, nullptr, nullptr, nullptr, 0);
}